// round 4
// baseline (speedup 1.0000x reference)
#include <cuda_runtime.h>

// SSIM loss: 1 - mean(ssim_map(clean, adv)), 11x11 gaussian sigma=1.5, zero SAME padding.
// d_in[0]=clean [32,3,512,512] f32, d_in[1]=adversarial. Output: 1 float.

#define IMG 512
#define TILE 32
#define HALO 5
#define EXT (TILE + 2 * HALO)   // 42
#define NPLANES (32 * 3)
#define NPIX (32.0 * 3.0 * 512.0 * 512.0)

typedef unsigned long long u64;

__device__ double g_ssim_acc = 0.0;

// ---- packed f32x2 helpers (ptxas will not emit FFMA2 from C++) ----
__device__ __forceinline__ u64 pack2(float x, float y) {
    u64 r; asm("mov.b64 %0, {%1, %2};" : "=l"(r) : "f"(x), "f"(y)); return r;
}
__device__ __forceinline__ float2 un2(u64 v) {
    float2 r; asm("mov.b64 {%0, %1}, %2;" : "=f"(r.x), "=f"(r.y) : "l"(v)); return r;
}
__device__ __forceinline__ u64 fma2(u64 a, u64 b, u64 c) {
    u64 d; asm("fma.rn.f32x2 %0, %1, %2, %3;" : "=l"(d) : "l"(a), "l"(b), "l"(c)); return d;
}
__device__ __forceinline__ u64 mul2(u64 a, u64 b) {
    u64 d; asm("mul.rn.f32x2 %0, %1, %2;" : "=l"(d) : "l"(a), "l"(b)); return d;
}
__device__ __forceinline__ u64 add2(u64 a, u64 b) {
    u64 d; asm("add.rn.f32x2 %0, %1, %2;" : "=l"(d) : "l"(a), "l"(b)); return d;
}

// Gaussian window, sigma=1.5, 11 taps, normalized.
#define W0 0.26601173f
#define W1 0.21300555f
#define W2 0.10936069f
#define W3 0.03600077f
#define W4 0.00759875f
#define W5 0.00102838f

__global__ void __launch_bounds__(256) ssim_tile_kernel(
    const float* __restrict__ clean, const float* __restrict__ adv)
{
    __shared__ __align__(16) u64 s_ca[EXT][EXT];   // packed (clean, adv)   14112 B
    __shared__ u64 s_mu[EXT][TILE];                // packed (m1, m2)       10752 B
    __shared__ u64 s_sq[EXT][TILE];                // packed (s11, s22)     10752 B
    __shared__ float s_xx[EXT][TILE];              // s12                    5376 B
    __shared__ float s_red[8];

    const float wf[11] = {W5, W4, W3, W2, W1, W0, W1, W2, W3, W4, W5};
    u64 wp[11];
    #pragma unroll
    for (int k = 0; k < 11; k++) wp[k] = pack2(wf[k], wf[k]);

    const int plane = blockIdx.z;
    const float* cp = clean + (size_t)plane * IMG * IMG;
    const float* ap = adv   + (size_t)plane * IMG * IMG;
    const int x0 = blockIdx.x * TILE;
    const int y0 = blockIdx.y * TILE;
    const int tid = threadIdx.x;

    // ---- load halo tile (zero padding outside image) ----
    #pragma unroll 2
    for (int idx = tid; idx < EXT * EXT; idx += 256) {
        int r = idx / EXT, c = idx - r * EXT;
        int gy = y0 - HALO + r;
        int gx = x0 - HALO + c;
        float cv = 0.f, av = 0.f;
        if ((unsigned)gy < IMG && (unsigned)gx < IMG) {
            cv = cp[gy * IMG + gx];
            av = ap[gy * IMG + gx];
        }
        s_ca[r][c] = pack2(cv, av);
    }
    __syncthreads();

    // ---- horizontal pass: 672 tasks = 42 rows x 16 column-pairs.
    //      Each task computes outputs c0, c0+1 from 12 u64 loaded as
    //      6x LDS.128 (16B lane stride -> conflict-free wavefronts). ----
    for (int idx = tid; idx < EXT * 16; idx += 256) {
        int r = idx >> 4;
        int c0 = (idx & 15) << 1;

        u64 v[12];
        const float4* src = (const float4*)&s_ca[r][c0];   // 16B aligned
        #pragma unroll
        for (int i = 0; i < 6; i++) {
            float4 f = src[i];
            v[2 * i]     = pack2(f.x, f.y);
            v[2 * i + 1] = pack2(f.z, f.w);
        }

        u64 ma = 0ull, sa = 0ull, mb = 0ull, sb = 0ull;
        float xa = 0.f, xb = 0.f;
        #pragma unroll
        for (int k = 0; k < 11; k++) {
            u64 va = v[k];
            u64 t = mul2(wp[k], va);       // (w*x, w*y)
            ma = add2(ma, t);
            sa = fma2(t, va, sa);
            float2 tv = un2(t);
            float2 vv = un2(va);
            xa = fmaf(tv.x, vv.y, xa);

            u64 vb = v[k + 1];
            u64 u = mul2(wp[k], vb);
            mb = add2(mb, u);
            sb = fma2(u, vb, sb);
            float2 uv = un2(u);
            float2 vw = un2(vb);
            xb = fmaf(uv.x, vw.y, xb);
        }
        s_mu[r][c0] = ma;  s_mu[r][c0 + 1] = mb;
        s_sq[r][c0] = sa;  s_sq[r][c0 + 1] = sb;
        s_xx[r][c0] = xa;  s_xx[r][c0 + 1] = xb;
    }
    __syncthreads();

    // ---- vertical pass: each thread computes 4 consecutive rows,
    //      loading the 15 covering intermediate rows exactly once.
    //      Lane-linear addressing: conflict-free. ----
    const float C1 = 1.0e-4f;
    const float C2 = 9.0e-4f;
    const int tx = tid & 31;
    const int ty = tid >> 5;        // 0..7
    const int rbase = ty * 4;       // output rows rbase..rbase+3

    u64 am[4] = {0ull, 0ull, 0ull, 0ull};
    u64 ae[4] = {0ull, 0ull, 0ull, 0ull};
    float a12[4] = {0.f, 0.f, 0.f, 0.f};

    #pragma unroll
    for (int j = 0; j < 15; j++) {
        int r = rbase + j;
        u64 mu = s_mu[r][tx];
        u64 sq = s_sq[r][tx];
        float xx = s_xx[r][tx];
        #pragma unroll
        for (int o = 0; o < 4; o++) {
            const int k = j - o;
            if (k >= 0 && k <= 10) {
                am[o] = fma2(wp[k], mu, am[o]);
                ae[o] = fma2(wp[k], sq, ae[o]);
                a12[o] = fmaf(wf[k], xx, a12[o]);
            }
        }
    }

    float local = 0.f;
    #pragma unroll
    for (int o = 0; o < 4; o++) {
        float2 m = un2(am[o]);
        float2 e = un2(ae[o]);
        float mu1_sq = m.x * m.x;
        float mu2_sq = m.y * m.y;
        float mu12   = m.x * m.y;
        float sig1  = e.x - mu1_sq;
        float sig2  = e.y - mu2_sq;
        float sig12 = a12[o] - mu12;
        float num = (2.f * mu12 + C1) * (2.f * sig12 + C2);
        float den = (mu1_sq + mu2_sq + C1) * (sig1 + sig2 + C2);
        local += __fdividef(num, den);
    }

    // ---- block reduction ----
    #pragma unroll
    for (int off = 16; off > 0; off >>= 1)
        local += __shfl_down_sync(0xFFFFFFFFu, local, off);
    if (tx == 0) s_red[ty] = local;
    __syncthreads();
    if (tid == 0) {
        float bs = 0.f;
        #pragma unroll
        for (int i = 0; i < 8; i++) bs += s_red[i];
        atomicAdd(&g_ssim_acc, (double)bs);
    }
}

// Reads the accumulator, writes the loss, resets for the next graph replay.
__global__ void finalize_kernel(float* out) {
    out[0] = 1.0f - (float)(g_ssim_acc / NPIX);
    g_ssim_acc = 0.0;
}

extern "C" void kernel_launch(void* const* d_in, const int* in_sizes, int n_in,
                              void* d_out, int out_size) {
    const float* clean = (const float*)d_in[0];
    const float* adv   = (const float*)d_in[1];
    float* out = (float*)d_out;

    dim3 grid(IMG / TILE, IMG / TILE, NPLANES);
    ssim_tile_kernel<<<grid, 256>>>(clean, adv);
    finalize_kernel<<<1, 1>>>(out);
}

// round 5
// speedup vs baseline: 1.6114x; 1.6114x over previous
#include <cuda_runtime.h>

// SSIM loss: 1 - mean(ssim_map(clean, adv)), 11x11 gaussian sigma=1.5, zero SAME padding.
// d_in[0]=clean [32,3,512,512] f32, d_in[1]=adversarial. Output: 1 float.

#define IMG 512
#define TILE 32
#define HALO 5
#define EXT (TILE + 2 * HALO)   // 42
#define NPLANES (32 * 3)
#define NPIX (32.0 * 3.0 * 512.0 * 512.0)

typedef unsigned long long u64;

__device__ double g_ssim_acc = 0.0;

// ---- packed f32x2 helpers (ptxas will not emit FFMA2 from C++) ----
__device__ __forceinline__ u64 pack2(float x, float y) {
    u64 r; asm("mov.b64 %0, {%1, %2};" : "=l"(r) : "f"(x), "f"(y)); return r;
}
__device__ __forceinline__ float2 un2(u64 v) {
    float2 r; asm("mov.b64 {%0, %1}, %2;" : "=f"(r.x), "=f"(r.y) : "l"(v)); return r;
}
__device__ __forceinline__ u64 fma2(u64 a, u64 b, u64 c) {
    u64 d; asm("fma.rn.f32x2 %0, %1, %2, %3;" : "=l"(d) : "l"(a), "l"(b), "l"(c)); return d;
}
__device__ __forceinline__ u64 mul2(u64 a, u64 b) {
    u64 d; asm("mul.rn.f32x2 %0, %1, %2;" : "=l"(d) : "l"(a), "l"(b)); return d;
}
__device__ __forceinline__ u64 add2(u64 a, u64 b) {
    u64 d; asm("add.rn.f32x2 %0, %1, %2;" : "=l"(d) : "l"(a), "l"(b)); return d;
}

// Gaussian window, sigma=1.5, 11 taps, normalized.
#define W0 0.26601173f
#define W1 0.21300555f
#define W2 0.10936069f
#define W3 0.03600077f
#define W4 0.00759875f
#define W5 0.00102838f

__global__ void __launch_bounds__(256, 5) ssim_tile_kernel(
    const float* __restrict__ clean, const float* __restrict__ adv)
{
    __shared__ u64 s_ca[EXT][EXT];        // packed (clean, adv)      14112 B
    __shared__ u64 s_mu[EXT][TILE];       // packed (m1, m2)          10752 B
    __shared__ u64 s_sq[EXT][TILE];       // packed (s11, s22)        10752 B
    __shared__ float s_xx[EXT][TILE];     // s12                       5376 B
    __shared__ float s_red[8];

    const float wf[11] = {W5, W4, W3, W2, W1, W0, W1, W2, W3, W4, W5};
    // 6 unique packed weights (window is symmetric) -> 12 regs, not 22.
    const u64 p0 = pack2(W0, W0), p1 = pack2(W1, W1), p2 = pack2(W2, W2);
    const u64 p3 = pack2(W3, W3), p4 = pack2(W4, W4), p5 = pack2(W5, W5);
    const u64 wp[11] = {p5, p4, p3, p2, p1, p0, p1, p2, p3, p4, p5};

    const int plane = blockIdx.z;
    const float* cp = clean + (size_t)plane * IMG * IMG;
    const float* ap = adv   + (size_t)plane * IMG * IMG;
    const int x0 = blockIdx.x * TILE;
    const int y0 = blockIdx.y * TILE;
    const int tid = threadIdx.x;

    // ---- load halo tile (zero padding outside image), incremental (r,c) ----
    {
        int r = tid / EXT;          // 256/42: r in 0..6 initially
        int c = tid - r * EXT;
        #pragma unroll
        for (int it = 0; it < 7; it++) {
            // idx = tid + it*256 ; valid while idx < EXT*EXT (last iter partial)
            if (it < 6 || r < EXT) {
                int gy = y0 - HALO + r;
                int gx = x0 - HALO + c;
                float cv = 0.f, av = 0.f;
                if ((unsigned)gy < IMG && (unsigned)gx < IMG) {
                    cv = cp[gy * IMG + gx];
                    av = ap[gy * IMG + gx];
                }
                s_ca[r][c] = pack2(cv, av);
            }
            // advance by 256 = 6*EXT + 4
            r += 6; c += 4;
            if (c >= EXT) { c -= EXT; r += 1; }
        }
    }
    __syncthreads();

    // ---- horizontal pass: 42 rows x 32 cols, packed accumulators ----
    for (int idx = tid; idx < EXT * TILE; idx += 256) {
        int r = idx >> 5, c = idx & 31;
        const u64* row = &s_ca[r][c];
        u64 m = 0ull, s = 0ull;
        float s12 = 0.f;
        #pragma unroll
        for (int k = 0; k < 11; k++) {
            u64 v = row[k];
            u64 t = mul2(wp[k], v);          // (w*x, w*y)
            m = add2(m, t);                  // (mu1, mu2)
            s = fma2(t, v, s);               // (E x^2, E y^2)
            float2 tv = un2(t);
            float2 vv = un2(v);
            s12 = fmaf(tv.x, vv.y, s12);     // E xy
        }
        s_mu[r][c] = m;
        s_sq[r][c] = s;
        s_xx[r][c] = s12;
    }
    __syncthreads();

    // ---- vertical pass: each thread computes 4 consecutive rows,
    //      loading the 15 covering intermediate rows exactly once ----
    const float C1 = 1.0e-4f;
    const float C2 = 9.0e-4f;
    const int tx = tid & 31;
    const int ty = tid >> 5;        // 0..7
    const int rbase = ty * 4;       // output rows rbase..rbase+3

    u64 am[4] = {0ull, 0ull, 0ull, 0ull};
    u64 ae[4] = {0ull, 0ull, 0ull, 0ull};
    float a12[4] = {0.f, 0.f, 0.f, 0.f};

    #pragma unroll
    for (int j = 0; j < 15; j++) {
        int r = rbase + j;
        u64 mu = s_mu[r][tx];
        u64 sq = s_sq[r][tx];
        float xx = s_xx[r][tx];
        #pragma unroll
        for (int o = 0; o < 4; o++) {
            const int k = j - o;
            if (k >= 0 && k <= 10) {
                am[o] = fma2(wp[k], mu, am[o]);
                ae[o] = fma2(wp[k], sq, ae[o]);
                a12[o] = fmaf(wf[k], xx, a12[o]);
            }
        }
    }

    float local = 0.f;
    #pragma unroll
    for (int o = 0; o < 4; o++) {
        float2 m = un2(am[o]);
        float2 e = un2(ae[o]);
        float mu1_sq = m.x * m.x;
        float mu2_sq = m.y * m.y;
        float mu12   = m.x * m.y;
        float sig1  = e.x - mu1_sq;
        float sig2  = e.y - mu2_sq;
        float sig12 = a12[o] - mu12;
        float num = (2.f * mu12 + C1) * (2.f * sig12 + C2);
        float den = (mu1_sq + mu2_sq + C1) * (sig1 + sig2 + C2);
        local += __fdividef(num, den);
    }

    // ---- block reduction ----
    #pragma unroll
    for (int off = 16; off > 0; off >>= 1)
        local += __shfl_down_sync(0xFFFFFFFFu, local, off);
    if (tx == 0) s_red[ty] = local;
    __syncthreads();
    if (tid == 0) {
        float bs = 0.f;
        #pragma unroll
        for (int i = 0; i < 8; i++) bs += s_red[i];
        atomicAdd(&g_ssim_acc, (double)bs);
    }
}

// Reads the accumulator, writes the loss, resets for the next graph replay.
__global__ void finalize_kernel(float* out) {
    out[0] = 1.0f - (float)(g_ssim_acc / NPIX);
    g_ssim_acc = 0.0;
}

extern "C" void kernel_launch(void* const* d_in, const int* in_sizes, int n_in,
                              void* d_out, int out_size) {
    const float* clean = (const float*)d_in[0];
    const float* adv   = (const float*)d_in[1];
    float* out = (float*)d_out;

    dim3 grid(IMG / TILE, IMG / TILE, NPLANES);
    ssim_tile_kernel<<<grid, 256>>>(clean, adv);
    finalize_kernel<<<1, 1>>>(out);
}